// round 1
// baseline (speedup 1.0000x reference)
#include <cuda_runtime.h>
#include <math.h>

// Problem dims (fixed by the dataset)
#define BB    8
#define CCH   512
#define HWP   256          // 16*16
#define NPIX  (BB*CCH*HWP) // 1,048,576

// ---------------- device scratch (no allocations allowed) ----------------
__device__ float g_m[HWP * 256];     // m[hw][t]
__device__ float g_myA[BB * HWP];    // (1 + A2)[b][hw]  (timestep-invariant)
__device__ float g_AM[NPIX];         // myA * x          (timestep-invariant)
__device__ float g_CW[4][NPIX];      // conv(AM, Wg)+bg  (timestep-invariant)
__device__ float g_G[4][NPIX];       // per-ts raw gate pre-activations
__device__ float g_h[NPIX];
__device__ float g_c[NPIX];

// ---------------- attention precompute ----------------
// m[hw][t] = sum_e WK[e] * WQ[hw*512 + e][t]
__global__ void k_m(const float* __restrict__ WQ, const float* __restrict__ WK) {
    int hw = blockIdx.x, t = threadIdx.x;
    const float* base = WQ + ((size_t)hw * 512) * 256 + t;
    float s = 0.f;
#pragma unroll 4
    for (int e = 0; e < 512; e++) s += WK[e] * base[(size_t)e * 256];
    g_m[hw * 256 + t] = s;
}

// scores -> softmax over H -> myA = 1 + attn*dot(WV,Wsum_w) + Wsum_b
__global__ void k_att(const float* __restrict__ txt, const float* __restrict__ WV,
                      const float* __restrict__ Wsw, const float* __restrict__ Wsb) {
    int b = blockIdx.x, hw = threadIdx.x;
    __shared__ float st[256];
    __shared__ float sc[256];
    st[hw] = txt[b * 256 + hw];
    __syncthreads();
    float s = 0.f;
#pragma unroll 4
    for (int t = 0; t < 256; t++) s += st[t] * g_m[hw * 256 + t];
    s /= sqrtf(512.0f);
    sc[hw] = s;
    __syncthreads();
    int w = hw & 15;
    float mx = -1e30f;
#pragma unroll
    for (int h2 = 0; h2 < 16; h2++) mx = fmaxf(mx, sc[h2 * 16 + w]);
    float den = 0.f;
#pragma unroll
    for (int h2 = 0; h2 < 16; h2++) den += expf(sc[h2 * 16 + w] - mx);
    float attn = expf(s - mx) / den;
    float vw = 0.f;
    for (int e = 0; e < 512; e++) vw += WV[e] * Wsw[e];
    g_myA[b * 256 + hw] = 1.f + attn * vw + Wsb[0];
}

// AM = myA * x (broadcast over channels)
__global__ void k_am(const float* __restrict__ x) {
    int idx = blockIdx.x * 256 + threadIdx.x;
    int b = idx >> 17;     // / (512*256)
    int hw = idx & 255;
    g_AM[idx] = g_myA[b * 256 + hw] * x[idx];
}

// ---------------- 3x3 conv, 512->512, 16x16 spatial, pad=1 ----------------
// Block: 256 threads = 8 cout-groups x 32 spatial threads.
// Each thread: 8 couts x (1 row x 8 cols). Cout tile = 64, Cin chunk = 32.
// grid: x = b*8 + coutTile (64), z = gate (4).
struct ConvArgs {
    const float* in;
    const float* W[4];
    const float* bias[4];
    const float* base[4];   // optional additive term (precomputed conv(AM,Wg)+bg)
    float* out[4];
};

#define SMEM_FLOATS (32 * 272 + 32 * 576)   // input planes (pad17) + weights
#define SMEM_BYTES  (SMEM_FLOATS * 4)

__global__ __launch_bounds__(256, 1) void k_conv(ConvArgs a) {
    extern __shared__ float sm[];
    float* sIn = sm;                 // [32][16*17]
    float* wsm = sm + 32 * 272;      // [32 cin][64 cout][9]

    int tid = threadIdx.x;
    int b = blockIdx.x & 7;
    int coTile = blockIdx.x >> 3;    // 0..7
    int gate = blockIdx.z;
    int cog = tid >> 5, s = tid & 31;
    int half = s >> 4, row = s & 15;
    int c0 = half * 8;

    const float* In = a.in + ((size_t)b * 512) * 256;
    const float* Wg = a.W[gate] + (size_t)coTile * 64 * 4608;

    float acc[8][8];
#pragma unroll
    for (int j = 0; j < 8; j++)
#pragma unroll
        for (int cx = 0; cx < 8; cx++) acc[j][cx] = 0.f;

    for (int cc = 0; cc < 16; cc++) {
        __syncthreads();
        // stage 32 input planes (padded row stride 17 to dodge bank conflicts)
        for (int i = tid; i < 32 * 256; i += 256) {
            int ci = i >> 8, hw = i & 255;
            sIn[ci * 272 + (hw >> 4) * 17 + (hw & 15)] = In[cc * 32 * 256 + i];
        }
        // stage weights [cin][cout][9]
        const float* Wc = Wg + cc * 288;
        for (int i = tid; i < 64 * 288; i += 256) {
            int co = i / 288, r = i - co * 288;
            int ci = r / 9, k = r - ci * 9;
            wsm[ci * 576 + co * 9 + k] = Wc[(size_t)co * 4608 + r];
        }
        __syncthreads();

#pragma unroll 1
        for (int ci = 0; ci < 32; ci++) {
            const float* P = sIn + ci * 272;
            float r0[10], r1[10], r2[10];
#pragma unroll
            for (int u = 0; u < 10; u++) {
                int col = c0 - 1 + u;
                bool cv = (col >= 0) && (col < 16);
                r1[u] = cv ? P[row * 17 + col] : 0.f;
                r0[u] = (cv && row > 0)  ? P[(row - 1) * 17 + col] : 0.f;
                r2[u] = (cv && row < 15) ? P[(row + 1) * 17 + col] : 0.f;
            }
            const float* wb = wsm + ci * 576 + cog * 72;
#pragma unroll
            for (int j = 0; j < 8; j++) {
                float w0 = wb[j*9+0], w1 = wb[j*9+1], w2 = wb[j*9+2];
                float w3 = wb[j*9+3], w4 = wb[j*9+4], w5 = wb[j*9+5];
                float w6 = wb[j*9+6], w7 = wb[j*9+7], w8 = wb[j*9+8];
#pragma unroll
                for (int cx = 0; cx < 8; cx++) {
                    float v = acc[j][cx];
                    v += w0 * r0[cx];     v += w1 * r0[cx + 1]; v += w2 * r0[cx + 2];
                    v += w3 * r1[cx];     v += w4 * r1[cx + 1]; v += w5 * r1[cx + 2];
                    v += w6 * r2[cx];     v += w7 * r2[cx + 1]; v += w8 * r2[cx + 2];
                    acc[j][cx] = v;
                }
            }
        }
    }

    // epilogue: + bias (+ optional precomputed base), vectorized stores
    const float* bias  = a.bias[gate];
    const float* basep = a.base[gate];
    float* outp = a.out[gate];
#pragma unroll
    for (int j = 0; j < 8; j++) {
        int co = coTile * 64 + cog * 8 + j;
        float bv = bias[co];
        size_t off = ((size_t)b * 512 + co) * 256 + row * 16 + c0;
        float4 o0 = make_float4(acc[j][0] + bv, acc[j][1] + bv, acc[j][2] + bv, acc[j][3] + bv);
        float4 o1 = make_float4(acc[j][4] + bv, acc[j][5] + bv, acc[j][6] + bv, acc[j][7] + bv);
        if (basep) {
            float4 b0 = *(const float4*)(basep + off);
            float4 b1 = *(const float4*)(basep + off + 4);
            o0.x += b0.x; o0.y += b0.y; o0.z += b0.z; o0.w += b0.w;
            o1.x += b1.x; o1.y += b1.y; o1.z += b1.z; o1.w += b1.w;
        }
        *(float4*)(outp + off)     = o0;
        *(float4*)(outp + off + 4) = o1;
    }
}

// ---------------- LSTM elementwise update ----------------
__global__ void k_update(const float* __restrict__ cprev, float* __restrict__ cnew,
                         float* __restrict__ hnew) {
    int idx = blockIdx.x * 256 + threadIdx.x;
    float gi = g_G[0][idx], gf = g_G[1][idx], gc = g_G[2][idx], go = g_G[3][idx];
    float i = 1.f / (1.f + expf(-gi));
    float f = 1.f / (1.f + expf(-gf));
    float g = tanhf(gc);
    float o = 1.f / (1.f + expf(-go));
    float c = g * i + f * cprev[idx];
    cnew[idx] = c;
    hnew[idx] = tanhf(c) * o;
}

// ---------------- launch ----------------
extern "C" void kernel_launch(void* const* d_in, const int* in_sizes, int n_in,
                              void* d_out, int out_size) {
    const float* x    = (const float*)d_in[0];
    const float* txt  = (const float*)d_in[1];
    // d_in[2..6] = Wa_w, Wa_b, Ua_w, Ua_b, Va_w : provably dead (softmax over size-1 axis == 1)
    const float* Wi_w = (const float*)d_in[7];
    const float* Wi_b = (const float*)d_in[8];
    const float* Ui_w = (const float*)d_in[9];
    const float* Ui_b = (const float*)d_in[10];
    const float* Wf_w = (const float*)d_in[11];
    const float* Wf_b = (const float*)d_in[12];
    const float* Uf_w = (const float*)d_in[13];
    const float* Uf_b = (const float*)d_in[14];
    const float* Wc_w = (const float*)d_in[15];
    const float* Wc_b = (const float*)d_in[16];
    const float* Uc_w = (const float*)d_in[17];
    const float* Uc_b = (const float*)d_in[18];
    const float* Wo_w = (const float*)d_in[19];
    const float* Wo_b = (const float*)d_in[20];
    const float* Uo_w = (const float*)d_in[21];
    const float* Uo_b = (const float*)d_in[22];
    const float* WQ   = (const float*)d_in[23];
    const float* WK   = (const float*)d_in[24];
    const float* WV   = (const float*)d_in[25];
    const float* Wsw  = (const float*)d_in[26];
    const float* Wsb  = (const float*)d_in[27];
    float* out = (float*)d_out;

    // scratch addresses
    float *pCW, *pG, *pAM, *pH, *pC;
    cudaGetSymbolAddress((void**)&pCW, g_CW);
    cudaGetSymbolAddress((void**)&pG,  g_G);
    cudaGetSymbolAddress((void**)&pAM, g_AM);
    cudaGetSymbolAddress((void**)&pH,  g_h);
    cudaGetSymbolAddress((void**)&pC,  g_c);

    cudaFuncSetAttribute(k_conv, cudaFuncAttributeMaxDynamicSharedMemorySize, SMEM_BYTES);

    // attention precompute (all timestep-invariant)
    k_m<<<256, 256>>>(WQ, WK);
    k_att<<<8, 256>>>(txt, WV, Wsw, Wsb);
    k_am<<<NPIX / 256, 256>>>(x);

    // precompute conv(AM, Wg) + bg once (gate order: i, f, c, o)
    {
        ConvArgs a;
        a.in = pAM;
        a.W[0] = Wi_w; a.W[1] = Wf_w; a.W[2] = Wc_w; a.W[3] = Wo_w;
        a.bias[0] = Wi_b; a.bias[1] = Wf_b; a.bias[2] = Wc_b; a.bias[3] = Wo_b;
        for (int g = 0; g < 4; g++) { a.base[g] = nullptr; a.out[g] = pCW + (size_t)g * NPIX; }
        k_conv<<<dim3(64, 1, 4), 256, SMEM_BYTES>>>(a);
    }

    // 4-timestep recurrence: only conv(h, Ug) per step
    for (int ts = 0; ts < 4; ts++) {
        ConvArgs a;
        a.in = (ts == 0) ? x : pH;
        a.W[0] = Ui_w; a.W[1] = Uf_w; a.W[2] = Uc_w; a.W[3] = Uo_w;
        a.bias[0] = Ui_b; a.bias[1] = Uf_b; a.bias[2] = Uc_b; a.bias[3] = Uo_b;
        for (int g = 0; g < 4; g++) {
            a.base[g] = pCW + (size_t)g * NPIX;
            a.out[g]  = pG + (size_t)g * NPIX;
        }
        k_conv<<<dim3(64, 1, 4), 256, SMEM_BYTES>>>(a);
        k_update<<<NPIX / 256, 256>>>((ts == 0) ? x : pC, pC,
                                      (ts == 3) ? out : pH);
    }
}

// round 4
// speedup vs baseline: 2.7660x; 2.7660x over previous
#include <cuda_runtime.h>
#include <cuda_bf16.h>
#include <stdint.h>
#include <math.h>

// Problem dims (fixed by the dataset)
#define BB    8
#define HWP   256
#define NPIX  (8*512*256)     // 1,048,576
#define KDIM  4608            // 512 cin * 9 taps
#define MROWS 2048            // 4 gates * 512 cout

// ---------------- device scratch (no allocations allowed) ----------------
__device__ float g_m[HWP * 256];
__device__ float g_myA[BB * HWP];
__device__ float g_AM[NPIX];
__device__ float g_CW[4][NPIX];        // conv(AM,Wg)+bg (timestep-invariant)
__device__ float g_G[4][NPIX];         // per-ts gate pre-activations
__device__ float g_h[NPIX];
__device__ float g_c[NPIX];
// split-bf16 weights, K reordered as k = tap*512 + cin. Set 0 = W gates, set 1 = U gates.
__device__ __align__(16) __nv_bfloat16 g_Whi[2][MROWS * KDIM];
__device__ __align__(16) __nv_bfloat16 g_Wlo[2][MROWS * KDIM];
// split-bf16 im2col of current conv input: X[bpix][tap*512+cin]
__device__ __align__(16) __nv_bfloat16 g_Xhi[2048 * KDIM];
__device__ __align__(16) __nv_bfloat16 g_Xlo[2048 * KDIM];

// ---------------- helpers ----------------
__device__ __forceinline__ uint32_t smem_u32(const void* p) {
    uint32_t a;
    asm("{ .reg .u64 t; cvta.to.shared.u64 t, %1; cvt.u32.u64 %0, t; }" : "=r"(a) : "l"(p));
    return a;
}
__device__ __forceinline__ void cp16(uint32_t smaddr, const void* gaddr) {
    asm volatile("cp.async.cg.shared.global [%0], [%1], 16;" :: "r"(smaddr), "l"(gaddr));
}
__device__ __forceinline__ void cp_commit() {
    asm volatile("cp.async.commit_group;" ::: "memory");
}
__device__ __forceinline__ void cp_wait1() {
    asm volatile("cp.async.wait_group 1;" ::: "memory");
}
__device__ __forceinline__ void cp_wait0() {
    asm volatile("cp.async.wait_group 0;" ::: "memory");
}
__device__ __forceinline__ void ldsm4(uint32_t* r, uint32_t addr) {
    asm volatile("ldmatrix.sync.aligned.m8n8.x4.shared.b16 {%0,%1,%2,%3}, [%4];"
                 : "=r"(r[0]), "=r"(r[1]), "=r"(r[2]), "=r"(r[3]) : "r"(addr));
}
__device__ __forceinline__ void mma16816(float* c, const uint32_t* A, const uint32_t* B) {
    asm volatile(
        "mma.sync.aligned.m16n8k16.row.col.f32.bf16.bf16.f32 "
        "{%0,%1,%2,%3}, {%4,%5,%6,%7}, {%8,%9}, {%0,%1,%2,%3};"
        : "+f"(c[0]), "+f"(c[1]), "+f"(c[2]), "+f"(c[3])
        : "r"(A[0]), "r"(A[1]), "r"(A[2]), "r"(A[3]), "r"(B[0]), "r"(B[1]));
}
__device__ __forceinline__ void split_bf16(float v, __nv_bfloat16& hi, __nv_bfloat16& lo) {
    hi = __float2bfloat16(v);
    lo = __float2bfloat16(v - __bfloat162float(hi));
}

// ---------------- attention precompute ----------------
__global__ void k_m(const float* __restrict__ WQ, const float* __restrict__ WK) {
    int hw = blockIdx.x, t = threadIdx.x;
    const float* base = WQ + ((size_t)hw * 512) * 256 + t;
    float s = 0.f;
#pragma unroll 4
    for (int e = 0; e < 512; e++) s += WK[e] * base[(size_t)e * 256];
    g_m[hw * 256 + t] = s;
}

__global__ void k_att(const float* __restrict__ txt, const float* __restrict__ WV,
                      const float* __restrict__ Wsw, const float* __restrict__ Wsb) {
    int b = blockIdx.x, hw = threadIdx.x;
    __shared__ float st[256];
    __shared__ float sc[256];
    st[hw] = txt[b * 256 + hw];
    __syncthreads();
    float s = 0.f;
#pragma unroll 4
    for (int t = 0; t < 256; t++) s += st[t] * g_m[hw * 256 + t];
    s /= sqrtf(512.0f);
    sc[hw] = s;
    __syncthreads();
    int w = hw & 15;
    float mx = -1e30f;
#pragma unroll
    for (int h2 = 0; h2 < 16; h2++) mx = fmaxf(mx, sc[h2 * 16 + w]);
    float den = 0.f;
#pragma unroll
    for (int h2 = 0; h2 < 16; h2++) den += expf(sc[h2 * 16 + w] - mx);
    float attn = expf(s - mx) / den;
    float vw = 0.f;
    for (int e = 0; e < 512; e++) vw += WV[e] * Wsw[e];
    g_myA[b * 256 + hw] = 1.f + attn * vw + Wsb[0];
}

__global__ void k_am(const float* __restrict__ x) {
    int idx = blockIdx.x * 256 + threadIdx.x;
    int b = idx >> 17;
    int hw = idx & 255;
    g_AM[idx] = g_myA[b * 256 + hw] * x[idx];
}

// ---------------- weight split + K-reorder ----------------
struct WPtrs { const float* p[8]; };  // Wi,Wf,Wc,Wo, Ui,Uf,Uc,Uo

__global__ void k_wsplit(WPtrs wp) {
    __shared__ float srow[KDIM];
    int bid = blockIdx.x;           // 0..4095
    int s = bid >> 11;              // set (0=W, 1=U)
    int m = bid & 2047;             // stacked row: g*512+cout
    const float* src = wp.p[s * 4 + (m >> 9)] + (size_t)(m & 511) * KDIM;
    for (int i = threadIdx.x; i < KDIM; i += 256) srow[i] = src[i];
    __syncthreads();
    __nv_bfloat16* dh = g_Whi[s] + (size_t)m * KDIM;
    __nv_bfloat16* dl = g_Wlo[s] + (size_t)m * KDIM;
    for (int k = threadIdx.x; k < KDIM; k += 256) {
        int tap = k >> 9, cin = k & 511;
        __nv_bfloat16 h, l;
        split_bf16(srow[cin * 9 + tap], h, l);
        dh[k] = h; dl[k] = l;
    }
}

// ---------------- im2col + split: X[bp][tap*512+cin] ----------------
#define IMS 49   // padded row stride in smem
__global__ void k_im2col(const float* __restrict__ In) {
    extern __shared__ float S2[];   // [512][49] : rows r-1,r,r+1 x 16 cols per cin
    int b = blockIdx.x >> 4;
    int r = blockIdx.x & 15;
    int tid = threadIdx.x;
    for (int i = tid; i < 512 * 48; i += 256) {
        int cin = i / 48, rem = i - cin * 48;
        int rr = rem >> 4, c = rem & 15;
        int sr = r + rr - 1;
        float v = (sr >= 0 && sr < 16) ? In[((size_t)(b * 512 + cin)) * 256 + sr * 16 + c] : 0.f;
        S2[cin * IMS + rem] = v;
    }
    __syncthreads();
    int warp = tid >> 5, lane = tid & 31;
    for (int t = warp; t < 144; t += 8) {
        int c = t / 9, tap = t - c * 9;
        int dr = tap / 3, dc = tap - dr * 3;
        int sc = c + dc - 1;
        bool valid = (sc >= 0) && (sc < 16);
        int jj = dr * 16 + sc;
        int bp = b * 256 + r * 16 + c;
        uint32_t* dh = (uint32_t*)(g_Xhi + (size_t)bp * KDIM + tap * 512);
        uint32_t* dl = (uint32_t*)(g_Xlo + (size_t)bp * KDIM + tap * 512);
#pragma unroll
        for (int q = 0; q < 8; q++) {
            int cin = q * 64 + lane * 2;
            float v0 = valid ? S2[cin * IMS + jj] : 0.f;
            float v1 = valid ? S2[(cin + 1) * IMS + jj] : 0.f;
            __nv_bfloat16 h0, l0, h1, l1;
            split_bf16(v0, h0, l0);
            split_bf16(v1, h1, l1);
            __nv_bfloat162 hh; hh.x = h0; hh.y = h1;
            __nv_bfloat162 ll; ll.x = l0; ll.y = l1;
            dh[q * 32 + lane] = *(uint32_t*)&hh;
            dl[q * 32 + lane] = *(uint32_t*)&ll;
        }
    }
}

// ---------------- HMMA GEMM: D[2048 x 2048] = Acat * X^T, split-bf16 x3 ----------------
// CTA tile 128x128, 8 warps (2x4), warp tile 64x32. K-chunk 32, cp.async double buffer.
struct GArgs {
    const __nv_bfloat16* Ahi;
    const __nv_bfloat16* Alo;
    const float* bias[4];
    const float* base;      // optional additive (g_CW), nullable
    float* out;
};

#define KC 32
#define NCHUNK (KDIM / KC)         // 144
#define ROWB 80                    // padded smem row stride (64B data + 16B pad)
#define ST_A (128 * ROWB)          // 10240 B per operand region
#define ST_BYTES (4 * ST_A)        // Ahi,Alo,Bhi,Blo = 40960 B per stage
#define GEMM_SMEM (2 * ST_BYTES)   // 81920 B

__global__ __launch_bounds__(256, 2) void k_gemm(GArgs a) {
    extern __shared__ __align__(128) char sm[];
    uint32_t usm = smem_u32(sm);
    int tid = threadIdx.x, wid = tid >> 5, lane = tid & 31;
    int mt = blockIdx.x;   // 0..15
    int nt = blockIdx.y;   // 0..15

    const __nv_bfloat16* srcs[4];
    srcs[0] = a.Ahi + (size_t)mt * 128 * KDIM;
    srcs[1] = a.Alo + (size_t)mt * 128 * KDIM;
    srcs[2] = g_Xhi + (size_t)nt * 128 * KDIM;
    srcs[3] = g_Xlo + (size_t)nt * 128 * KDIM;

    int m0 = (wid >> 2) * 64;
    int n0 = (wid & 3) * 32;

    float acc[4][4][4];
#pragma unroll
    for (int mf = 0; mf < 4; mf++)
#pragma unroll
        for (int nf = 0; nf < 4; nf++)
#pragma unroll
            for (int q = 0; q < 4; q++) acc[mf][nf][q] = 0.f;

    int row = tid >> 2, seg = tid & 3;   // 64 row-slots x 4 segs; each thread does rows row, row+64

    // prologue: chunk 0 -> stage 0  (full 128 rows per region: 2 halves)
    {
#pragma unroll
        for (int rg = 0; rg < 4; rg++) {
#pragma unroll
            for (int h = 0; h < 2; h++) {
                int rr = row + h * 64;
                uint32_t d = usm + rg * ST_A + rr * ROWB + seg * 16;
                cp16(d, srcs[rg] + (size_t)rr * KDIM + seg * 8);
            }
        }
        cp_commit();
    }

    // lane address pieces for ldmatrix (within a stage region)
    uint32_t a_lane_off = (uint32_t)((lane & 15) * ROWB + (lane >> 4) * 16);      // + mf*16*ROWB + k0*2
    uint32_t b_lane_off = (uint32_t)((((lane >> 4) << 3) + (lane & 7)) * ROWB + ((lane >> 3) & 1) * 16); // + pair*16*ROWB + k0*2

    for (int kc = 0; kc < NCHUNK; kc++) {
        int st = kc & 1;
        if (kc + 1 < NCHUNK) {
            int st2 = st ^ 1;
            size_t koff = (size_t)(kc + 1) * KC;
#pragma unroll
            for (int rg = 0; rg < 4; rg++) {
#pragma unroll
                for (int h = 0; h < 2; h++) {
                    int rr = row + h * 64;
                    uint32_t d = usm + st2 * ST_BYTES + rg * ST_A + rr * ROWB + seg * 16;
                    cp16(d, srcs[rg] + (size_t)rr * KDIM + koff + seg * 8);
                }
            }
            cp_commit();
            cp_wait1();
        } else {
            cp_wait0();
        }
        __syncthreads();

        uint32_t sAhi = usm + st * ST_BYTES;
        uint32_t sAlo = sAhi + ST_A;
        uint32_t sBhi = sAlo + ST_A;
        uint32_t sBlo = sBhi + ST_A;

#pragma unroll
        for (int ks = 0; ks < 2; ks++) {
            uint32_t kb = ks * 32;     // k0*2 bytes (k0 = ks*16)
            uint32_t Af[4][4], Bf[4][2], Bl[4][2];
            // A hi frags
#pragma unroll
            for (int mf = 0; mf < 4; mf++)
                ldsm4(Af[mf], sAhi + (uint32_t)(m0 + mf * 16) * ROWB + kb + a_lane_off);
            // B hi frags
#pragma unroll
            for (int p = 0; p < 2; p++) {
                uint32_t t[4];
                ldsm4(t, sBhi + (uint32_t)(n0 + p * 16) * ROWB + kb + b_lane_off);
                Bf[2 * p][0] = t[0]; Bf[2 * p][1] = t[1];
                Bf[2 * p + 1][0] = t[2]; Bf[2 * p + 1][1] = t[3];
            }
            // hi * hi
#pragma unroll
            for (int mf = 0; mf < 4; mf++)
#pragma unroll
                for (int nf = 0; nf < 4; nf++) mma16816(acc[mf][nf], Af[mf], Bf[nf]);
            // B lo frags, hi * lo
#pragma unroll
            for (int p = 0; p < 2; p++) {
                uint32_t t[4];
                ldsm4(t, sBlo + (uint32_t)(n0 + p * 16) * ROWB + kb + b_lane_off);
                Bl[2 * p][0] = t[0]; Bl[2 * p][1] = t[1];
                Bl[2 * p + 1][0] = t[2]; Bl[2 * p + 1][1] = t[3];
            }
#pragma unroll
            for (int mf = 0; mf < 4; mf++)
#pragma unroll
                for (int nf = 0; nf < 4; nf++) mma16816(acc[mf][nf], Af[mf], Bl[nf]);
            // A lo frags (overwrite Af), lo * hi
#pragma unroll
            for (int mf = 0; mf < 4; mf++)
                ldsm4(Af[mf], sAlo + (uint32_t)(m0 + mf * 16) * ROWB + kb + a_lane_off);
#pragma unroll
            for (int mf = 0; mf < 4; mf++)
#pragma unroll
                for (int nf = 0; nf < 4; nf++) mma16816(acc[mf][nf], Af[mf], Bf[nf]);
        }
        __syncthreads();
    }

    // epilogue: bias + optional base add, float2 stores
    const float* basep = a.base;
#pragma unroll
    for (int mf = 0; mf < 4; mf++) {
        int mg = mt * 128 + m0 + mf * 16 + (lane >> 2);
        int g = mg >> 9, cout = mg & 511;
        float bv0 = a.bias[g][cout];
        float bv1 = a.bias[g][cout + 8];
        size_t ob = (size_t)g * NPIX + (size_t)cout * 256;
#pragma unroll
        for (int nf = 0; nf < 4; nf++) {
            int n = nt * 128 + n0 + nf * 8 + ((lane & 3) << 1);
            int b = n >> 8, hw = n & 255;
            size_t i0 = ob + (size_t)b * 512 * 256 + hw;
            size_t i1 = i0 + 8 * 256;
            float2 v0 = make_float2(acc[mf][nf][0] + bv0, acc[mf][nf][1] + bv0);
            float2 v1 = make_float2(acc[mf][nf][2] + bv1, acc[mf][nf][3] + bv1);
            if (basep) {
                float2 t0 = *(const float2*)(basep + i0);
                float2 t1 = *(const float2*)(basep + i1);
                v0.x += t0.x; v0.y += t0.y;
                v1.x += t1.x; v1.y += t1.y;
            }
            *(float2*)(a.out + i0) = v0;
            *(float2*)(a.out + i1) = v1;
        }
    }
}

// ---------------- LSTM elementwise update ----------------
__global__ void k_update(const float* __restrict__ cprev, float* __restrict__ cnew,
                         float* __restrict__ hnew) {
    int idx = blockIdx.x * 256 + threadIdx.x;
    float gi = g_G[0][idx], gf = g_G[1][idx], gc = g_G[2][idx], go = g_G[3][idx];
    float i = 1.f / (1.f + expf(-gi));
    float f = 1.f / (1.f + expf(-gf));
    float g = tanhf(gc);
    float o = 1.f / (1.f + expf(-go));
    float c = g * i + f * cprev[idx];
    cnew[idx] = c;
    hnew[idx] = tanhf(c) * o;
}

// ---------------- launch ----------------
extern "C" void kernel_launch(void* const* d_in, const int* in_sizes, int n_in,
                              void* d_out, int out_size) {
    const float* x    = (const float*)d_in[0];
    const float* txt  = (const float*)d_in[1];
    // d_in[2..6] = Wa_w, Wa_b, Ua_w, Ua_b, Va_w : dead (softmax over size-1 axis == 1)
    const float* Wi_w = (const float*)d_in[7];
    const float* Wi_b = (const float*)d_in[8];
    const float* Ui_w = (const float*)d_in[9];
    const float* Ui_b = (const float*)d_in[10];
    const float* Wf_w = (const float*)d_in[11];
    const float* Wf_b = (const float*)d_in[12];
    const float* Uf_w = (const float*)d_in[13];
    const float* Uf_b = (const float*)d_in[14];
    const float* Wc_w = (const float*)d_in[15];
    const float* Wc_b = (const float*)d_in[16];
    const float* Uc_w = (const float*)d_in[17];
    const float* Uc_b = (const float*)d_in[18];
    const float* Wo_w = (const float*)d_in[19];
    const float* Wo_b = (const float*)d_in[20];
    const float* Uo_w = (const float*)d_in[21];
    const float* Uo_b = (const float*)d_in[22];
    const float* WQ   = (const float*)d_in[23];
    const float* WK   = (const float*)d_in[24];
    const float* WV   = (const float*)d_in[25];
    const float* Wsw  = (const float*)d_in[26];
    const float* Wsb  = (const float*)d_in[27];
    float* out = (float*)d_out;

    float *pCW, *pG, *pAM, *pH, *pC;
    __nv_bfloat16 *pWhi, *pWlo;
    cudaGetSymbolAddress((void**)&pCW, g_CW);
    cudaGetSymbolAddress((void**)&pG,  g_G);
    cudaGetSymbolAddress((void**)&pAM, g_AM);
    cudaGetSymbolAddress((void**)&pH,  g_h);
    cudaGetSymbolAddress((void**)&pC,  g_c);
    cudaGetSymbolAddress((void**)&pWhi, g_Whi);
    cudaGetSymbolAddress((void**)&pWlo, g_Wlo);

    cudaFuncSetAttribute(k_im2col, cudaFuncAttributeMaxDynamicSharedMemorySize, 512 * IMS * 4);
    cudaFuncSetAttribute(k_gemm, cudaFuncAttributeMaxDynamicSharedMemorySize, GEMM_SMEM);

    // weight split (both sets)
    WPtrs wp;
    wp.p[0] = Wi_w; wp.p[1] = Wf_w; wp.p[2] = Wc_w; wp.p[3] = Wo_w;
    wp.p[4] = Ui_w; wp.p[5] = Uf_w; wp.p[6] = Uc_w; wp.p[7] = Uo_w;
    k_wsplit<<<4096, 256>>>(wp);

    // attention precompute
    k_m<<<256, 256>>>(WQ, WK);
    k_att<<<8, 256>>>(txt, WV, Wsw, Wsb);
    k_am<<<NPIX / 256, 256>>>(x);

    // precompute conv(AM, Wg) + bg once
    k_im2col<<<128, 256, 512 * IMS * 4>>>(pAM);
    {
        GArgs ga;
        ga.Ahi = pWhi;                       // set 0 (W gates)
        ga.Alo = pWlo;
        ga.bias[0] = Wi_b; ga.bias[1] = Wf_b; ga.bias[2] = Wc_b; ga.bias[3] = Wo_b;
        ga.base = nullptr;
        ga.out = pCW;
        k_gemm<<<dim3(16, 16), 256, GEMM_SMEM>>>(ga);
    }

    // 4-timestep recurrence: conv(h, Ug) + CW per step
    for (int ts = 0; ts < 4; ts++) {
        k_im2col<<<128, 256, 512 * IMS * 4>>>((ts == 0) ? x : pH);
        GArgs gu;
        gu.Ahi = pWhi + (size_t)MROWS * KDIM;  // set 1 (U gates)
        gu.Alo = pWlo + (size_t)MROWS * KDIM;
        gu.bias[0] = Ui_b; gu.bias[1] = Uf_b; gu.bias[2] = Uc_b; gu.bias[3] = Uo_b;
        gu.base = pCW;
        gu.out = pG;
        k_gemm<<<dim3(16, 16), 256, GEMM_SMEM>>>(gu);
        k_update<<<NPIX / 256, 256>>>((ts == 0) ? x : pC, pC,
                                      (ts == 3) ? out : pH);
    }
}

// round 5
// speedup vs baseline: 3.6672x; 1.3258x over previous
#include <cuda_runtime.h>
#include <cuda_fp16.h>
#include <stdint.h>
#include <math.h>

// Problem dims (fixed by the dataset)
#define BB    8
#define HWP   256
#define NPIX  (8*512*256)     // 1,048,576
#define KDIM  4608            // 512 cin * 9 taps
#define MROWS 2048            // 4 gates * 512 cout

// ---------------- device scratch (no allocations allowed) ----------------
__device__ float g_m[HWP * 256];
__device__ float g_myA[BB * HWP];
__device__ float g_AM[NPIX];
__device__ float g_CW[4][NPIX];        // conv(AM,Wg)+bg (timestep-invariant)
__device__ float g_G[4][NPIX];         // per-ts gate pre-activations
__device__ float g_h[NPIX];
__device__ float g_c[NPIX];
// split-fp16 weights, K reordered as k = tap*512 + cin. Set 0 = W gates, set 1 = U gates.
__device__ __align__(16) __half g_Whi[2][MROWS * KDIM];
__device__ __align__(16) __half g_Wlo[2][MROWS * KDIM];
// single-fp16 im2col of current conv input: X[bpix][tap*512+cin]
__device__ __align__(16) __half g_X[2048 * KDIM];

// ---------------- helpers ----------------
__device__ __forceinline__ uint32_t smem_u32(const void* p) {
    uint32_t a;
    asm("{ .reg .u64 t; cvta.to.shared.u64 t, %1; cvt.u32.u64 %0, t; }" : "=r"(a) : "l"(p));
    return a;
}
__device__ __forceinline__ void cp16(uint32_t smaddr, const void* gaddr) {
    asm volatile("cp.async.cg.shared.global [%0], [%1], 16;" :: "r"(smaddr), "l"(gaddr));
}
__device__ __forceinline__ void cp_commit() {
    asm volatile("cp.async.commit_group;" ::: "memory");
}
__device__ __forceinline__ void cp_wait1() {
    asm volatile("cp.async.wait_group 1;" ::: "memory");
}
__device__ __forceinline__ void cp_wait0() {
    asm volatile("cp.async.wait_group 0;" ::: "memory");
}
__device__ __forceinline__ void ldsm4(uint32_t* r, uint32_t addr) {
    asm volatile("ldmatrix.sync.aligned.m8n8.x4.shared.b16 {%0,%1,%2,%3}, [%4];"
                 : "=r"(r[0]), "=r"(r[1]), "=r"(r[2]), "=r"(r[3]) : "r"(addr));
}
__device__ __forceinline__ void mma16816(float* c, const uint32_t* A, const uint32_t* B) {
    asm volatile(
        "mma.sync.aligned.m16n8k16.row.col.f32.f16.f16.f32 "
        "{%0,%1,%2,%3}, {%4,%5,%6,%7}, {%8,%9}, {%0,%1,%2,%3};"
        : "+f"(c[0]), "+f"(c[1]), "+f"(c[2]), "+f"(c[3])
        : "r"(A[0]), "r"(A[1]), "r"(A[2]), "r"(A[3]), "r"(B[0]), "r"(B[1]));
}
__device__ __forceinline__ void split_f16(float v, __half& hi, __half& lo) {
    hi = __float2half_rn(v);
    lo = __float2half_rn(v - __half2float(hi));
}

// ---------------- attention precompute ----------------
__global__ void k_m(const float* __restrict__ WQ, const float* __restrict__ WK) {
    int hw = blockIdx.x, t = threadIdx.x;
    const float* base = WQ + ((size_t)hw * 512) * 256 + t;
    float s = 0.f;
#pragma unroll 4
    for (int e = 0; e < 512; e++) s += WK[e] * base[(size_t)e * 256];
    g_m[hw * 256 + t] = s;
}

__global__ void k_att(const float* __restrict__ txt, const float* __restrict__ WV,
                      const float* __restrict__ Wsw, const float* __restrict__ Wsb) {
    int b = blockIdx.x, hw = threadIdx.x;
    __shared__ float st[256];
    __shared__ float sc[256];
    st[hw] = txt[b * 256 + hw];
    __syncthreads();
    float s = 0.f;
#pragma unroll 4
    for (int t = 0; t < 256; t++) s += st[t] * g_m[hw * 256 + t];
    s /= sqrtf(512.0f);
    sc[hw] = s;
    __syncthreads();
    int w = hw & 15;
    float mx = -1e30f;
#pragma unroll
    for (int h2 = 0; h2 < 16; h2++) mx = fmaxf(mx, sc[h2 * 16 + w]);
    float den = 0.f;
#pragma unroll
    for (int h2 = 0; h2 < 16; h2++) den += expf(sc[h2 * 16 + w] - mx);
    float attn = expf(s - mx) / den;
    float vw = 0.f;
    for (int e = 0; e < 512; e++) vw += WV[e] * Wsw[e];
    g_myA[b * 256 + hw] = 1.f + attn * vw + Wsb[0];
}

__global__ void k_am(const float* __restrict__ x) {
    int idx = blockIdx.x * 256 + threadIdx.x;
    int b = idx >> 17;
    int hw = idx & 255;
    g_AM[idx] = g_myA[b * 256 + hw] * x[idx];
}

// ---------------- weight split + K-reorder ----------------
struct WPtrs { const float* p[8]; };  // Wi,Wf,Wc,Wo, Ui,Uf,Uc,Uo

__global__ void k_wsplit(WPtrs wp) {
    __shared__ float srow[KDIM];
    int bid = blockIdx.x;           // 0..4095
    int s = bid >> 11;              // set (0=W, 1=U)
    int m = bid & 2047;             // stacked row: g*512+cout
    const float* src = wp.p[s * 4 + (m >> 9)] + (size_t)(m & 511) * KDIM;
    for (int i = threadIdx.x; i < KDIM; i += 256) srow[i] = src[i];
    __syncthreads();
    __half* dh = g_Whi[s] + (size_t)m * KDIM;
    __half* dl = g_Wlo[s] + (size_t)m * KDIM;
    for (int k = threadIdx.x; k < KDIM; k += 256) {
        int tap = k >> 9, cin = k & 511;
        __half h, l;
        split_f16(srow[cin * 9 + tap], h, l);
        dh[k] = h; dl[k] = l;
    }
}

// ---------------- im2col (single fp16): X[bp][tap*512+cin] ----------------
#define IMS 49   // padded row stride in smem
__global__ void k_im2col(const float* __restrict__ In) {
    extern __shared__ float S2[];   // [512][49] : rows r-1,r,r+1 x 16 cols per cin
    int b = blockIdx.x >> 4;
    int r = blockIdx.x & 15;
    int tid = threadIdx.x;
    for (int i = tid; i < 512 * 48; i += 256) {
        int cin = i / 48, rem = i - cin * 48;
        int rr = rem >> 4, c = rem & 15;
        int sr = r + rr - 1;
        float v = (sr >= 0 && sr < 16) ? In[((size_t)(b * 512 + cin)) * 256 + sr * 16 + c] : 0.f;
        S2[cin * IMS + rem] = v;
    }
    __syncthreads();
    int warp = tid >> 5, lane = tid & 31;
    for (int t = warp; t < 144; t += 8) {
        int c = t / 9, tap = t - c * 9;
        int dr = tap / 3, dc = tap - dr * 3;
        int sc = c + dc - 1;
        bool valid = (sc >= 0) && (sc < 16);
        int jj = dr * 16 + sc;
        int bp = b * 256 + r * 16 + c;
        uint32_t* dh = (uint32_t*)(g_X + (size_t)bp * KDIM + tap * 512);
#pragma unroll
        for (int q = 0; q < 8; q++) {
            int cin = q * 64 + lane * 2;
            float v0 = valid ? S2[cin * IMS + jj] : 0.f;
            float v1 = valid ? S2[(cin + 1) * IMS + jj] : 0.f;
            __half2 hh = __halves2half2(__float2half_rn(v0), __float2half_rn(v1));
            dh[q * 32 + lane] = *(uint32_t*)&hh;
        }
    }
}

// ---------------- HMMA GEMM: D = Acat * X^T, fp16 split-A x2 passes ----------------
// CTA tile 128x128, 8 warps (2x4), warp tile 64x32. K-chunk 32, cp.async double buffer.
struct GArgs {
    const __half* Ahi;
    const __half* Alo;
    const float* bias[4];
    const float* base;      // optional additive (g_CW), nullable
    float* out;
};

#define KC 32
#define NCHUNK (KDIM / KC)         // 144
#define ROWB 80                    // padded smem row stride (64B data + 16B pad)
#define ST_A (128 * ROWB)          // 10240 B per operand region
#define ST_BYTES (3 * ST_A)        // Ahi, Alo, B = 30720 B per stage
#define GEMM_SMEM (2 * ST_BYTES)   // 61440 B

__global__ __launch_bounds__(256, 2) void k_gemm(GArgs a) {
    extern __shared__ __align__(128) char sm[];
    uint32_t usm = smem_u32(sm);
    int tid = threadIdx.x, wid = tid >> 5, lane = tid & 31;
    int mt = blockIdx.x;   // 0..15
    int nt = blockIdx.y;   // 0..15

    const __half* srcs[3];
    srcs[0] = a.Ahi + (size_t)mt * 128 * KDIM;
    srcs[1] = a.Alo + (size_t)mt * 128 * KDIM;
    srcs[2] = g_X + (size_t)nt * 128 * KDIM;

    int m0 = (wid >> 2) * 64;
    int n0 = (wid & 3) * 32;

    float acc[4][4][4];
#pragma unroll
    for (int mf = 0; mf < 4; mf++)
#pragma unroll
        for (int nf = 0; nf < 4; nf++)
#pragma unroll
            for (int q = 0; q < 4; q++) acc[mf][nf][q] = 0.f;

    int row = tid >> 2, seg = tid & 3;   // 64 row-slots x 4 segs; each thread does rows row, row+64

    // prologue: chunk 0 -> stage 0  (full 128 rows per region: 2 halves)
    {
#pragma unroll
        for (int rg = 0; rg < 3; rg++) {
#pragma unroll
            for (int h = 0; h < 2; h++) {
                int rr = row + h * 64;
                uint32_t d = usm + rg * ST_A + rr * ROWB + seg * 16;
                cp16(d, srcs[rg] + (size_t)rr * KDIM + seg * 8);
            }
        }
        cp_commit();
    }

    // lane address pieces for ldmatrix (within a stage region)
    uint32_t a_lane_off = (uint32_t)((lane & 15) * ROWB + (lane >> 4) * 16);      // + mf*16*ROWB + k0*2
    uint32_t b_lane_off = (uint32_t)((((lane >> 4) << 3) + (lane & 7)) * ROWB + ((lane >> 3) & 1) * 16); // + pair*16*ROWB + k0*2

    for (int kc = 0; kc < NCHUNK; kc++) {
        int st = kc & 1;
        if (kc + 1 < NCHUNK) {
            int st2 = st ^ 1;
            size_t koff = (size_t)(kc + 1) * KC;
#pragma unroll
            for (int rg = 0; rg < 3; rg++) {
#pragma unroll
                for (int h = 0; h < 2; h++) {
                    int rr = row + h * 64;
                    uint32_t d = usm + st2 * ST_BYTES + rg * ST_A + rr * ROWB + seg * 16;
                    cp16(d, srcs[rg] + (size_t)rr * KDIM + koff + seg * 8);
                }
            }
            cp_commit();
            cp_wait1();
        } else {
            cp_wait0();
        }
        __syncthreads();

        uint32_t sAhi = usm + st * ST_BYTES;
        uint32_t sAlo = sAhi + ST_A;
        uint32_t sB   = sAlo + ST_A;

#pragma unroll
        for (int ks = 0; ks < 2; ks++) {
            uint32_t kb = ks * 32;     // k0*2 bytes (k0 = ks*16)
            uint32_t Af[4][4], Bf[4][2];
            // A hi frags
#pragma unroll
            for (int mf = 0; mf < 4; mf++)
                ldsm4(Af[mf], sAhi + (uint32_t)(m0 + mf * 16) * ROWB + kb + a_lane_off);
            // B frags
#pragma unroll
            for (int p = 0; p < 2; p++) {
                uint32_t t[4];
                ldsm4(t, sB + (uint32_t)(n0 + p * 16) * ROWB + kb + b_lane_off);
                Bf[2 * p][0] = t[0]; Bf[2 * p][1] = t[1];
                Bf[2 * p + 1][0] = t[2]; Bf[2 * p + 1][1] = t[3];
            }
            // hi * B
#pragma unroll
            for (int mf = 0; mf < 4; mf++)
#pragma unroll
                for (int nf = 0; nf < 4; nf++) mma16816(acc[mf][nf], Af[mf], Bf[nf]);
            // A lo frags (overwrite Af), lo * B
#pragma unroll
            for (int mf = 0; mf < 4; mf++)
                ldsm4(Af[mf], sAlo + (uint32_t)(m0 + mf * 16) * ROWB + kb + a_lane_off);
#pragma unroll
            for (int mf = 0; mf < 4; mf++)
#pragma unroll
                for (int nf = 0; nf < 4; nf++) mma16816(acc[mf][nf], Af[mf], Bf[nf]);
        }
        __syncthreads();
    }

    // epilogue: bias + optional base add, float2 stores
    const float* basep = a.base;
#pragma unroll
    for (int mf = 0; mf < 4; mf++) {
        int mg = mt * 128 + m0 + mf * 16 + (lane >> 2);
        int g = mg >> 9, cout = mg & 511;
        float bv0 = a.bias[g][cout];
        float bv1 = a.bias[g][cout + 8];
        size_t ob = (size_t)g * NPIX + (size_t)cout * 256;
#pragma unroll
        for (int nf = 0; nf < 4; nf++) {
            int n = nt * 128 + n0 + nf * 8 + ((lane & 3) << 1);
            int b = n >> 8, hw = n & 255;
            size_t i0 = ob + (size_t)b * 512 * 256 + hw;
            size_t i1 = i0 + 8 * 256;
            float2 v0 = make_float2(acc[mf][nf][0] + bv0, acc[mf][nf][1] + bv0);
            float2 v1 = make_float2(acc[mf][nf][2] + bv1, acc[mf][nf][3] + bv1);
            if (basep) {
                float2 t0 = *(const float2*)(basep + i0);
                float2 t1 = *(const float2*)(basep + i1);
                v0.x += t0.x; v0.y += t0.y;
                v1.x += t1.x; v1.y += t1.y;
            }
            *(float2*)(a.out + i0) = v0;
            *(float2*)(a.out + i1) = v1;
        }
    }
}

// ---------------- LSTM elementwise update ----------------
__global__ void k_update(const float* __restrict__ cprev, float* __restrict__ cnew,
                         float* __restrict__ hnew) {
    int idx = blockIdx.x * 256 + threadIdx.x;
    float gi = g_G[0][idx], gf = g_G[1][idx], gc = g_G[2][idx], go = g_G[3][idx];
    float i = 1.f / (1.f + expf(-gi));
    float f = 1.f / (1.f + expf(-gf));
    float g = tanhf(gc);
    float o = 1.f / (1.f + expf(-go));
    float c = g * i + f * cprev[idx];
    cnew[idx] = c;
    hnew[idx] = tanhf(c) * o;
}

// ---------------- launch ----------------
extern "C" void kernel_launch(void* const* d_in, const int* in_sizes, int n_in,
                              void* d_out, int out_size) {
    const float* x    = (const float*)d_in[0];
    const float* txt  = (const float*)d_in[1];
    // d_in[2..6] = Wa_w, Wa_b, Ua_w, Ua_b, Va_w : dead (softmax over size-1 axis == 1)
    const float* Wi_w = (const float*)d_in[7];
    const float* Wi_b = (const float*)d_in[8];
    const float* Ui_w = (const float*)d_in[9];
    const float* Ui_b = (const float*)d_in[10];
    const float* Wf_w = (const float*)d_in[11];
    const float* Wf_b = (const float*)d_in[12];
    const float* Uf_w = (const float*)d_in[13];
    const float* Uf_b = (const float*)d_in[14];
    const float* Wc_w = (const float*)d_in[15];
    const float* Wc_b = (const float*)d_in[16];
    const float* Uc_w = (const float*)d_in[17];
    const float* Uc_b = (const float*)d_in[18];
    const float* Wo_w = (const float*)d_in[19];
    const float* Wo_b = (const float*)d_in[20];
    const float* Uo_w = (const float*)d_in[21];
    const float* Uo_b = (const float*)d_in[22];
    const float* WQ   = (const float*)d_in[23];
    const float* WK   = (const float*)d_in[24];
    const float* WV   = (const float*)d_in[25];
    const float* Wsw  = (const float*)d_in[26];
    const float* Wsb  = (const float*)d_in[27];
    float* out = (float*)d_out;

    float *pCW, *pG, *pAM, *pH, *pC;
    __half *pWhi, *pWlo;
    cudaGetSymbolAddress((void**)&pCW, g_CW);
    cudaGetSymbolAddress((void**)&pG,  g_G);
    cudaGetSymbolAddress((void**)&pAM, g_AM);
    cudaGetSymbolAddress((void**)&pH,  g_h);
    cudaGetSymbolAddress((void**)&pC,  g_c);
    cudaGetSymbolAddress((void**)&pWhi, g_Whi);
    cudaGetSymbolAddress((void**)&pWlo, g_Wlo);

    cudaFuncSetAttribute(k_im2col, cudaFuncAttributeMaxDynamicSharedMemorySize, 512 * IMS * 4);
    cudaFuncSetAttribute(k_gemm, cudaFuncAttributeMaxDynamicSharedMemorySize, GEMM_SMEM);

    // weight split (both sets)
    WPtrs wp;
    wp.p[0] = Wi_w; wp.p[1] = Wf_w; wp.p[2] = Wc_w; wp.p[3] = Wo_w;
    wp.p[4] = Ui_w; wp.p[5] = Uf_w; wp.p[6] = Uc_w; wp.p[7] = Uo_w;
    k_wsplit<<<4096, 256>>>(wp);

    // attention precompute
    k_m<<<256, 256>>>(WQ, WK);
    k_att<<<8, 256>>>(txt, WV, Wsw, Wsb);
    k_am<<<NPIX / 256, 256>>>(x);

    // precompute conv(AM, Wg) + bg once
    k_im2col<<<128, 256, 512 * IMS * 4>>>(pAM);
    {
        GArgs ga;
        ga.Ahi = pWhi;                       // set 0 (W gates)
        ga.Alo = pWlo;
        ga.bias[0] = Wi_b; ga.bias[1] = Wf_b; ga.bias[2] = Wc_b; ga.bias[3] = Wo_b;
        ga.base = nullptr;
        ga.out = pCW;
        k_gemm<<<dim3(16, 16), 256, GEMM_SMEM>>>(ga);
    }

    // 4-timestep recurrence: conv(h, Ug) + CW per step
    for (int ts = 0; ts < 4; ts++) {
        k_im2col<<<128, 256, 512 * IMS * 4>>>((ts == 0) ? x : pH);
        GArgs gu;
        gu.Ahi = pWhi + (size_t)MROWS * KDIM;  // set 1 (U gates)
        gu.Alo = pWlo + (size_t)MROWS * KDIM;
        gu.bias[0] = Ui_b; gu.bias[1] = Uf_b; gu.bias[2] = Uc_b; gu.bias[3] = Uo_b;
        gu.base = pCW;
        gu.out = pG;
        k_gemm<<<dim3(16, 16), 256, GEMM_SMEM>>>(gu);
        k_update<<<NPIX / 256, 256>>>((ts == 0) ? x : pC, pC,
                                      (ts == 3) ? out : pH);
    }
}

// round 7
// speedup vs baseline: 7.5305x; 2.0535x over previous
#include <cuda_runtime.h>
#include <cuda_fp16.h>
#include <stdint.h>
#include <math.h>

// Problem dims (fixed by the dataset)
#define BB    8
#define HWP   256
#define NPIX  (8*512*256)     // 1,048,576
#define KDIM  4608            // 512 cin * 9 taps
#define MROWS 2048            // 4 gates * 512 cout

// ---------------- device scratch (no allocations allowed) ----------------
__device__ float g_m[HWP * 256];
__device__ float g_myA[BB * HWP];
__device__ float g_CW[4][NPIX];        // conv(AM,Wg)+bg (timestep-invariant)
__device__ float g_G[4][NPIX];         // per-ts gate pre-activations
__device__ float g_h[NPIX];
__device__ float g_c[NPIX];
// fp16 weights, K reordered as k = tap*512 + cin. Set 0 = W gates, set 1 = U gates.
__device__ __align__(16) __half g_Wh[2][MROWS * KDIM];
// transposed fp16 image of current conv input: Xt[b][hw][cin]
__device__ __align__(16) __half g_Xt[2048 * 512];

// ---------------- helpers ----------------
__device__ __forceinline__ uint32_t smem_u32(const void* p) {
    uint32_t a;
    asm("{ .reg .u64 t; cvta.to.shared.u64 t, %1; cvt.u32.u64 %0, t; }" : "=r"(a) : "l"(p));
    return a;
}
__device__ __forceinline__ void cp16(uint32_t smaddr, const void* gaddr) {
    asm volatile("cp.async.cg.shared.global [%0], [%1], 16;" :: "r"(smaddr), "l"(gaddr));
}
// zero-fill variant: src_size 0 -> 16 bytes of zeros, no memory access needed
__device__ __forceinline__ void cp16z(uint32_t smaddr, const void* gaddr, uint32_t srcsz) {
    asm volatile("cp.async.cg.shared.global [%0], [%1], 16, %2;"
                 :: "r"(smaddr), "l"(gaddr), "r"(srcsz));
}
__device__ __forceinline__ void cp_commit() {
    asm volatile("cp.async.commit_group;" ::: "memory");
}
__device__ __forceinline__ void cp_wait1() {
    asm volatile("cp.async.wait_group 1;" ::: "memory");
}
__device__ __forceinline__ void cp_wait0() {
    asm volatile("cp.async.wait_group 0;" ::: "memory");
}
__device__ __forceinline__ void ldsm4(uint32_t* r, uint32_t addr) {
    asm volatile("ldmatrix.sync.aligned.m8n8.x4.shared.b16 {%0,%1,%2,%3}, [%4];"
                 : "=r"(r[0]), "=r"(r[1]), "=r"(r[2]), "=r"(r[3]) : "r"(addr));
}
__device__ __forceinline__ void mma16816(float* c, const uint32_t* A, const uint32_t* B) {
    asm volatile(
        "mma.sync.aligned.m16n8k16.row.col.f32.f16.f16.f32 "
        "{%0,%1,%2,%3}, {%4,%5,%6,%7}, {%8,%9}, {%0,%1,%2,%3};"
        : "+f"(c[0]), "+f"(c[1]), "+f"(c[2]), "+f"(c[3])
        : "r"(A[0]), "r"(A[1]), "r"(A[2]), "r"(A[3]), "r"(B[0]), "r"(B[1]));
}

// ---------------- attention precompute ----------------
__global__ void k_m(const float* __restrict__ WQ, const float* __restrict__ WK) {
    int hw = blockIdx.x, t = threadIdx.x;
    const float* base = WQ + ((size_t)hw * 512) * 256 + t;
    float s = 0.f;
#pragma unroll 4
    for (int e = 0; e < 512; e++) s += WK[e] * base[(size_t)e * 256];
    g_m[hw * 256 + t] = s;
}

__global__ void k_att(const float* __restrict__ txt, const float* __restrict__ WV,
                      const float* __restrict__ Wsw, const float* __restrict__ Wsb) {
    int b = blockIdx.x, hw = threadIdx.x;
    __shared__ float st[256];
    __shared__ float sc[256];
    st[hw] = txt[b * 256 + hw];
    __syncthreads();
    float s = 0.f;
#pragma unroll 4
    for (int t = 0; t < 256; t++) s += st[t] * g_m[hw * 256 + t];
    s /= sqrtf(512.0f);
    sc[hw] = s;
    __syncthreads();
    int w = hw & 15;
    float mx = -1e30f;
#pragma unroll
    for (int h2 = 0; h2 < 16; h2++) mx = fmaxf(mx, sc[h2 * 16 + w]);
    float den = 0.f;
#pragma unroll
    for (int h2 = 0; h2 < 16; h2++) den += expf(sc[h2 * 16 + w] - mx);
    float attn = expf(s - mx) / den;
    float vw = 0.f;
    for (int e = 0; e < 512; e++) vw += WV[e] * Wsw[e];
    g_myA[b * 256 + hw] = 1.f + attn * vw + Wsb[0];
}

// ---------------- weight convert + K-reorder (fp16, single) ----------------
struct WPtrs { const float* p[8]; };  // Wi,Wf,Wc,Wo, Ui,Uf,Uc,Uo

__global__ void k_wsplit(WPtrs wp) {
    __shared__ float srow[KDIM];
    int bid = blockIdx.x;           // 0..4095
    int s = bid >> 11;              // set (0=W, 1=U)
    int m = bid & 2047;             // stacked row: g*512+cout
    const float* src = wp.p[s * 4 + (m >> 9)] + (size_t)(m & 511) * KDIM;
    for (int i = threadIdx.x; i < KDIM; i += 256) srow[i] = src[i];
    __syncthreads();
    __half* dh = g_Wh[s] + (size_t)m * KDIM;
    for (int k = threadIdx.x; k < KDIM; k += 256) {
        int tap = k >> 9, cin = k & 511;
        dh[k] = __float2half_rn(srow[cin * 9 + tap]);
    }
}

// ---------------- prep: transpose [b][cin][hw] -> Xt[b][hw][cin] fp16 ----------------
// optional per-pixel scale (myA) applied during transpose.
__global__ void k_prep(const float* __restrict__ In, int scaled) {
    __shared__ float T[64][65];
    int hwT = blockIdx.x;     // 0..3 (64 hw each)
    int cinT = blockIdx.y;    // 0..7 (64 cin each)
    int b = blockIdx.z;       // 0..7
    int tid = threadIdx.x;
#pragma unroll
    for (int i = 0; i < 16; i++) {
        int idx = i * 256 + tid;
        int ci = idx >> 6, hw = idx & 63;
        T[ci][hw] = In[((size_t)(b * 512 + cinT * 64 + ci)) * 256 + hwT * 64 + hw];
    }
    __syncthreads();
#pragma unroll
    for (int i = 0; i < 16; i++) {
        int idx = i * 256 + tid;
        int hw = idx >> 6, ci = idx & 63;
        float v = T[ci][hw];
        if (scaled) v *= g_myA[b * 256 + hwT * 64 + hw];
        g_Xt[((size_t)(b * 256 + hwT * 64 + hw)) * 512 + cinT * 64 + ci] = __float2half_rn(v);
    }
}

// ---------------- HMMA GEMM with implicit im2col (shift-GEMM) ----------------
// D[2048 x 2048] = W * im2col(Xt)^T. CTA tile 128x128, 8 warps, warp tile 64x32.
// K = 9 taps * 512 cin, chunk = 64 (one 128B swizzled row), double buffered.
struct GArgs {
    const __half* Aw;       // fp16 weights, [2048][KDIM], K = tap*512+cin
    const float* bias[4];
    const float* base;      // optional additive (g_CW), nullable
    float* out;
};

#define NCH 72                     // KDIM / 64
#define REGB 16384                 // 128 rows * 128 B per region
#define STG2 (2 * REGB)            // A + B per stage
#define GEMM_SMEM (2 * STG2)       // 65536 B

__global__ __launch_bounds__(256, 2) void k_gemm(GArgs a) {
    extern __shared__ __align__(128) char sm[];
    uint32_t usm = smem_u32(sm);
    int tid = threadIdx.x, wid = tid >> 5, lane = tid & 31;
    int mt = blockIdx.x;   // 0..15
    int nt = blockIdx.y;   // 0..15

    const __half* Aw = a.Aw + (size_t)mt * 128 * KDIM;

    int m0 = (wid >> 2) * 64;
    int n0 = (wid & 3) * 32;

    float acc[4][4][4];
#pragma unroll
    for (int mf = 0; mf < 4; mf++)
#pragma unroll
        for (int nf = 0; nf < 4; nf++)
#pragma unroll
            for (int q = 0; q < 4; q++) acc[mf][nf][q] = 0.f;

    // ---- loader role: 4 (row,seg) slots per thread per region ----
    int segq = tid & 7;            // 16B segment within 128B row
    int row0 = tid >> 3;           // 0..31
    uint32_t dstoff[4];
    const __half* ArowP[4];
    int pbase[4], pr[4], pc[4];
#pragma unroll
    for (int i = 0; i < 4; i++) {
        int row = row0 + i * 32;
        dstoff[i] = (uint32_t)(row * 128 + ((segq ^ (row & 7)) << 4));
        ArowP[i] = Aw + (size_t)row * KDIM + segq * 8;
        int p = nt * 128 + row;
        pbase[i] = (p >> 8) * 256;
        pr[i] = (p >> 4) & 15;
        pc[i] = p & 15;
    }

    // loader for chunk kc into stage st
    auto load_chunk = [&](int kc, int st) {
        int tap = kc >> 3, sub = kc & 7;
        int dr = (tap >= 6) ? 2 : ((tap >= 3) ? 1 : 0);
        int dc = tap - dr * 3;
        int koff = kc * 64;
        int cin0 = sub * 64 + segq * 8;
        uint32_t sA = usm + st * STG2;
        uint32_t sB = sA + REGB;
#pragma unroll
        for (int i = 0; i < 4; i++) {
            cp16(sA + dstoff[i], ArowP[i] + koff);
            int r2 = pr[i] + dr - 1, c2 = pc[i] + dc - 1;
            bool ok = ((unsigned)r2 < 16u) && ((unsigned)c2 < 16u);
            int pix = ok ? (pbase[i] + (r2 << 4) + c2) : 0;
            cp16z(sB + dstoff[i], g_Xt + (size_t)pix * 512 + cin0, ok ? 16u : 0u);
        }
        cp_commit();
    };

    load_chunk(0, 0);   // prologue

    // ldmatrix lane pieces
    int laneA = lane & 15, cA = lane >> 4;
    int laneB = ((lane >> 4) << 3) + (lane & 7), cB = (lane >> 3) & 1;

    for (int kc = 0; kc < NCH; kc++) {
        int st = kc & 1;
        if (kc + 1 < NCH) {
            load_chunk(kc + 1, st ^ 1);
            cp_wait1();
        } else {
            cp_wait0();
        }
        __syncthreads();

        uint32_t sA = usm + st * STG2;
        uint32_t sB = sA + REGB;

#pragma unroll
        for (int ks = 0; ks < 4; ks++) {
            uint32_t Af[4][4], Bf[4][2];
#pragma unroll
            for (int mf = 0; mf < 4; mf++) {
                int rowL = m0 + mf * 16 + laneA;
                int cu = 2 * ks + cA;
                ldsm4(Af[mf], sA + (uint32_t)(rowL << 7) + (uint32_t)(((cu ^ (rowL & 7))) << 4));
            }
#pragma unroll
            for (int p = 0; p < 2; p++) {
                int rowL = n0 + p * 16 + laneB;
                int cu = 2 * ks + cB;
                uint32_t t[4];
                ldsm4(t, sB + (uint32_t)(rowL << 7) + (uint32_t)(((cu ^ (rowL & 7))) << 4));
                Bf[2 * p][0] = t[0]; Bf[2 * p][1] = t[1];
                Bf[2 * p + 1][0] = t[2]; Bf[2 * p + 1][1] = t[3];
            }
#pragma unroll
            for (int mf = 0; mf < 4; mf++)
#pragma unroll
                for (int nf = 0; nf < 4; nf++) mma16816(acc[mf][nf], Af[mf], Bf[nf]);
        }
        __syncthreads();
    }

    // epilogue: bias + optional base add, float2 stores
    const float* basep = a.base;
#pragma unroll
    for (int mf = 0; mf < 4; mf++) {
        int mg = mt * 128 + m0 + mf * 16 + (lane >> 2);
        int g = mg >> 9, cout = mg & 511;
        float bv0 = a.bias[g][cout];
        float bv1 = a.bias[g][cout + 8];
        size_t ob = (size_t)g * NPIX + (size_t)cout * 256;
#pragma unroll
        for (int nf = 0; nf < 4; nf++) {
            int n = nt * 128 + n0 + nf * 8 + ((lane & 3) << 1);
            int b = n >> 8, hw = n & 255;
            size_t i0 = ob + (size_t)b * 512 * 256 + hw;
            size_t i1 = i0 + 8 * 256;
            float2 v0 = make_float2(acc[mf][nf][0] + bv0, acc[mf][nf][1] + bv0);
            float2 v1 = make_float2(acc[mf][nf][2] + bv1, acc[mf][nf][3] + bv1);
            if (basep) {
                float2 t0 = *(const float2*)(basep + i0);
                float2 t1 = *(const float2*)(basep + i1);
                v0.x += t0.x; v0.y += t0.y;
                v1.x += t1.x; v1.y += t1.y;
            }
            *(float2*)(a.out + i0) = v0;
            *(float2*)(a.out + i1) = v1;
        }
    }
}

// ---------------- LSTM elementwise update ----------------
__global__ void k_update(const float* __restrict__ cprev, float* __restrict__ cnew,
                         float* __restrict__ hnew) {
    int idx = blockIdx.x * 256 + threadIdx.x;
    float gi = g_G[0][idx], gf = g_G[1][idx], gc = g_G[2][idx], go = g_G[3][idx];
    float i = 1.f / (1.f + expf(-gi));
    float f = 1.f / (1.f + expf(-gf));
    float g = tanhf(gc);
    float o = 1.f / (1.f + expf(-go));
    float c = g * i + f * cprev[idx];
    cnew[idx] = c;
    hnew[idx] = tanhf(c) * o;
}

// ---------------- launch ----------------
extern "C" void kernel_launch(void* const* d_in, const int* in_sizes, int n_in,
                              void* d_out, int out_size) {
    const float* x    = (const float*)d_in[0];
    const float* txt  = (const float*)d_in[1];
    // d_in[2..6] = Wa_w, Wa_b, Ua_w, Ua_b, Va_w : dead (softmax over size-1 axis == 1)
    const float* Wi_w = (const float*)d_in[7];
    const float* Wi_b = (const float*)d_in[8];
    const float* Ui_w = (const float*)d_in[9];
    const float* Ui_b = (const float*)d_in[10];
    const float* Wf_w = (const float*)d_in[11];
    const float* Wf_b = (const float*)d_in[12];
    const float* Uf_w = (const float*)d_in[13];
    const float* Uf_b = (const float*)d_in[14];
    const float* Wc_w = (const float*)d_in[15];
    const float* Wc_b = (const float*)d_in[16];
    const float* Uc_w = (const float*)d_in[17];
    const float* Uc_b = (const float*)d_in[18];
    const float* Wo_w = (const float*)d_in[19];
    const float* Wo_b = (const float*)d_in[20];
    const float* Uo_w = (const float*)d_in[21];
    const float* Uo_b = (const float*)d_in[22];
    const float* WQ   = (const float*)d_in[23];
    const float* WK   = (const float*)d_in[24];
    const float* WV   = (const float*)d_in[25];
    const float* Wsw  = (const float*)d_in[26];
    const float* Wsb  = (const float*)d_in[27];
    float* out = (float*)d_out;

    float *pCW, *pG, *pH, *pC;
    __half *pWh;
    cudaGetSymbolAddress((void**)&pCW, g_CW);
    cudaGetSymbolAddress((void**)&pG,  g_G);
    cudaGetSymbolAddress((void**)&pH,  g_h);
    cudaGetSymbolAddress((void**)&pC,  g_c);
    cudaGetSymbolAddress((void**)&pWh, g_Wh);

    cudaFuncSetAttribute(k_gemm, cudaFuncAttributeMaxDynamicSharedMemorySize, GEMM_SMEM);

    // weight convert (both sets)
    WPtrs wp;
    wp.p[0] = Wi_w; wp.p[1] = Wf_w; wp.p[2] = Wc_w; wp.p[3] = Wo_w;
    wp.p[4] = Ui_w; wp.p[5] = Uf_w; wp.p[6] = Uc_w; wp.p[7] = Uo_w;
    k_wsplit<<<4096, 256>>>(wp);

    // attention precompute
    k_m<<<256, 256>>>(WQ, WK);
    k_att<<<8, 256>>>(txt, WV, Wsw, Wsb);

    // precompute conv(AM, Wg) + bg once (AM = myA*x applied inside prep)
    k_prep<<<dim3(4, 8, 8), 256>>>(x, 1);
    {
        GArgs ga;
        ga.Aw = pWh;                         // set 0 (W gates)
        ga.bias[0] = Wi_b; ga.bias[1] = Wf_b; ga.bias[2] = Wc_b; ga.bias[3] = Wo_b;
        ga.base = nullptr;
        ga.out = pCW;
        k_gemm<<<dim3(16, 16), 256, GEMM_SMEM>>>(ga);
    }

    // 4-timestep recurrence: conv(h, Ug) + CW per step
    for (int ts = 0; ts < 4; ts++) {
        k_prep<<<dim3(4, 8, 8), 256>>>((ts == 0) ? x : pH, 0);
        GArgs gu;
        gu.Aw = pWh + (size_t)MROWS * KDIM;   // set 1 (U gates)
        gu.bias[0] = Ui_b; gu.bias[1] = Uf_b; gu.bias[2] = Uc_b; gu.bias[3] = Uo_b;
        gu.base = pCW;
        gu.out = pG;
        k_gemm<<<dim3(16, 16), 256, GEMM_SMEM>>>(gu);
        k_update<<<NPIX / 256, 256>>>((ts == 0) ? x : pC, pC,
                                      (ts == 3) ? out : pH);
    }
}